// round 2
// baseline (speedup 1.0000x reference)
#include <cuda_runtime.h>
#include <cstdint>

// Problem constants (fixed shapes per reference)
#define NPTS   100000
#define PPROP  256
#define RFEAT  256
#define CO     21        // C+1
#define HALF   128       // feature half per block
#define NCHUNK 74        // point chunks (74*1352 >= 100000)
#define CHUNK  1352
#define TILE   64        // points staged per tile

// Scratch (allocation-free rule: __device__ globals)
__device__ float g_partial[2][NCHUNK][PPROP][HALF];   // ~19.4 MB
__device__ float g_pcounts[NCHUNK][PPROP];
__device__ float g_cls[PPROP * CO];
__device__ float g_obj[PPROP * CO];

// ---------------------------------------------------------------------------
// Kernel 1: sparse ROI pooling.
// grid = (NCHUNK, 2), block = 256 threads.
// blockIdx.y selects feature half [h*128, h*128+128).
// Warp w owns proposals [32w, 32w+32); accumulator lives in registers:
// lane l holds feats [4l, 4l+4) for each of its 32 proposals.
// ---------------------------------------------------------------------------
__global__ __launch_bounds__(256, 1)
void pool_kernel(const float* __restrict__ proposals,
                 const float* __restrict__ xyz,
                 const float* __restrict__ feats)
{
    const int chunk = blockIdx.x;
    const int h     = blockIdx.y;
    const int tid   = threadIdx.x;
    const int w     = tid >> 5;
    const int l     = tid & 31;

    __shared__ float lox[PPROP], loy[PPROP], loz[PPROP];
    __shared__ float hix[PPROP], hiy[PPROP], hiz[PPROP];
    __shared__ float sx[TILE], sy[TILE], sz[TILE];
    __shared__ float4 sf[TILE * 32];                 // [64][128 floats] = 32 KB
    __shared__ unsigned long long tmask[PPROP];      // per-proposal point bitmap

    // Box bounds, bit-exact vs reference (no FMA contraction).
    {
        const float cx = proposals[tid * 6 + 0];
        const float cy = proposals[tid * 6 + 1];
        const float cz = proposals[tid * 6 + 2];
        const float hx = __fmul_rn(proposals[tid * 6 + 3], 0.5f);
        const float hy = __fmul_rn(proposals[tid * 6 + 4], 0.5f);
        const float hz = __fmul_rn(proposals[tid * 6 + 5], 0.5f);
        lox[tid] = __fsub_rn(cx, hx);  hix[tid] = __fadd_rn(cx, hx);
        loy[tid] = __fsub_rn(cy, hy);  hiy[tid] = __fadd_rn(cy, hy);
        loz[tid] = __fsub_rn(cz, hz);  hiz[tid] = __fadd_rn(cz, hz);
    }

    float4 acc[32];
#pragma unroll
    for (int i = 0; i < 32; i++) acc[i] = make_float4(0.f, 0.f, 0.f, 0.f);
    float cnt = 0.f;   // thread tid counts membership of proposal p = tid

    const int base = chunk * CHUNK;
    const int nPts = (NPTS - base < CHUNK) ? (NPTS - base) : CHUNK;

    const float alox = lox[tid], ahix = hix[tid];
    const float aloy = loy[tid], ahiy = hiy[tid];
    const float aloz = loz[tid], ahiz = hiz[tid];
    __syncthreads();   // bounds visible (also covers the SoA reads above via same-thread)

    for (int t0 = 0; t0 < nPts; t0 += TILE) {
        const int tn = (nPts - t0 < TILE) ? (nPts - t0) : TILE;

        __syncthreads();   // previous tile fully consumed before restaging

        // Stage xyz
        if (tid < tn) {
            const int gi = base + t0 + tid;
            sx[tid] = xyz[gi * 3 + 0];
            sy[tid] = xyz[gi * 3 + 1];
            sz[tid] = xyz[gi * 3 + 2];
        }
        // Stage feature half-rows (coalesced float4)
        {
            const float4* gf = reinterpret_cast<const float4*>(feats);
            const int nv = tn * 32;
            for (int j = tid; j < nv; j += 256) {
                const int i = j >> 5, f = j & 31;
                sf[(i << 5) + f] = gf[(size_t)(base + t0 + i) * (RFEAT / 4) + h * 32 + f];
            }
        }
        __syncthreads();

        // Transposed masks: thread tid = proposal tid, 64-bit point bitmap
        {
            unsigned long long m = 0ull;
            for (int i = 0; i < tn; i++) {
                const float x = sx[i], y = sy[i], z = sz[i];
                const bool in = (x >= alox) & (x <= ahix) &
                                (y >= aloy) & (y <= ahiy) &
                                (z >= aloz) & (z <= ahiz);
                m |= ((unsigned long long)in) << i;
            }
            tmask[tid] = m;
            cnt += (float)__popcll(m);
        }
        __syncthreads();

        // Accumulate: register accumulator, compile-time proposal index
#pragma unroll
        for (int pl = 0; pl < 32; pl++) {
            unsigned long long m = tmask[(w << 5) + pl];   // warp-uniform broadcast
            while (m) {
                const int i = __ffsll((long long)m) - 1;
                m &= (m - 1);
                const float4 v = sf[(i << 5) + l];
                acc[pl].x += v.x; acc[pl].y += v.y;
                acc[pl].z += v.z; acc[pl].w += v.w;
            }
        }
    }

    // Write partial sums (coalesced)
    float* outp = &g_partial[h][chunk][0][0];
#pragma unroll
    for (int pl = 0; pl < 32; pl++) {
        const int p = (w << 5) + pl;
        reinterpret_cast<float4*>(outp + p * HALF)[l] = acc[pl];
    }
    if (h == 0) g_pcounts[chunk][tid] = cnt;
}

// ---------------------------------------------------------------------------
// Kernel 2: reduce partials -> roi feats -> cls/obj logits.
// grid = 256 (one block per proposal), block = 128 threads.
// ---------------------------------------------------------------------------
__global__ __launch_bounds__(128)
void reduce_kernel(const float* __restrict__ W_cls, const float* __restrict__ b_cls,
                   const float* __restrict__ W_obj, const float* __restrict__ b_obj)
{
    const int p = blockIdx.x;
    const int tid = threadIdx.x;

    __shared__ float roi[RFEAT];
    __shared__ float scnt[128];

    // Count reduction
    float c = 0.f;
    for (int cidx = tid; cidx < NCHUNK; cidx += 128) c += g_pcounts[cidx][p];
    scnt[tid] = c;
    __syncthreads();
    for (int s = 64; s > 0; s >>= 1) {
        if (tid < s) scnt[tid] += scnt[tid + s];
        __syncthreads();
    }
    const float inv = 1.0f / fmaxf(scnt[0], 1.0f);

    // Sum partials (coalesced over tid)
    float s0 = 0.f, s1 = 0.f;
    for (int cidx = 0; cidx < NCHUNK; cidx++) {
        s0 += g_partial[0][cidx][p][tid];
        s1 += g_partial[1][cidx][p][tid];
    }
    roi[tid]       = s0 * inv;
    roi[tid + 128] = s1 * inv;
    __syncthreads();

    // Logits: 42 dot products of length 256
    if (tid < 2 * CO) {
        const bool isobj = tid >= CO;
        const int  j     = isobj ? tid - CO : tid;
        const float* Wm  = isobj ? W_obj : W_cls;
        float a = isobj ? b_obj[j] : b_cls[j];
        for (int f = 0; f < RFEAT; f++) a += roi[f] * Wm[f * CO + j];
        (isobj ? g_obj : g_cls)[p * CO + j] = a;
    }
}

// ---------------------------------------------------------------------------
// Kernel 3: softmaxes + product. 1 block, 256 threads (thread = proposal row).
// ---------------------------------------------------------------------------
__global__ __launch_bounds__(256)
void softmax_kernel(float* __restrict__ out)
{
    const int tid = threadIdx.x;
    __shared__ float cmax[CO], csum[CO];

    // cls softmax over axis=1 (row tid)
    float clsp[CO];
    {
        float m = -3.4e38f;
        float lg[CO];
        for (int j = 0; j < CO; j++) { lg[j] = g_cls[tid * CO + j]; m = fmaxf(m, lg[j]); }
        float s = 0.f;
        for (int j = 0; j < CO; j++) { lg[j] = __expf(lg[j] - m) ; s += lg[j]; }
        // use precise expf for safety
        s = 0.f;
        for (int j = 0; j < CO; j++) { lg[j] = expf(g_cls[tid * CO + j] - m); s += lg[j]; }
        const float invs = 1.0f / s;
        for (int j = 0; j < CO; j++) clsp[j] = lg[j] * invs;
    }

    // obj column stats (axis=0)
    if (tid < CO) {
        float m = -3.4e38f;
        for (int p = 0; p < PPROP; p++) m = fmaxf(m, g_obj[p * CO + tid]);
        float s = 0.f;
        for (int p = 0; p < PPROP; p++) s += expf(g_obj[p * CO + tid] - m);
        cmax[tid] = m;
        csum[tid] = s;
    }
    __syncthreads();

    for (int j = 0; j < CO; j++) {
        const float op = expf(g_obj[tid * CO + j] - cmax[j]) / csum[j];
        out[tid * CO + j] = clsp[j] * op;
    }
}

// ---------------------------------------------------------------------------
extern "C" void kernel_launch(void* const* d_in, const int* in_sizes, int n_in,
                              void* d_out, int out_size)
{
    const float* proposals = (const float*)d_in[0];   // [256,6]
    const float* input_xyz = (const float*)d_in[1];   // [100000,3]
    const float* seg_feats = (const float*)d_in[2];   // [100000,256]
    const float* W_cls     = (const float*)d_in[3];   // [256,21]
    const float* b_cls     = (const float*)d_in[4];   // [21]
    const float* W_obj     = (const float*)d_in[5];   // [256,21]
    const float* b_obj     = (const float*)d_in[6];   // [21]
    float* out = (float*)d_out;                       // [256,21]

    (void)in_sizes; (void)n_in; (void)out_size;

    pool_kernel<<<dim3(NCHUNK, 2), 256>>>(proposals, input_xyz, seg_feats);
    reduce_kernel<<<PPROP, 128>>>(W_cls, b_cls, W_obj, b_obj);
    softmax_kernel<<<1, 256>>>(out);
}

// round 3
// speedup vs baseline: 1.3437x; 1.3437x over previous
#include <cuda_runtime.h>
#include <cstdint>

#define NPTS   100000
#define PPROP  256
#define RFEAT  256
#define CO     21
#define NCHUNK 74
#define CHUNK  1352      // 74*1352 = 100048 >= 100000
#define TILE   32        // points staged per tile
#define PG     64        // proposals per block

// Scratch (__device__ globals: allocation-free rule)
__device__ float g_partial[NCHUNK][PPROP][RFEAT];   // 19.4 MB
__device__ float g_pcounts[NCHUNK][PPROP];
__device__ float g_cls[PPROP * CO];
__device__ float g_obj[PPROP * CO];

// ---------------------------------------------------------------------------
// Kernel 1: sparse ROI pooling.
// grid = (74 chunks, 4 proposal-groups), block = 256 threads, 2 CTAs/SM.
// Masks computed ONCE per (chunk, proposal): thread t masks proposal (t&63)
// over points [8q, 8q+8), q = t>>6, via per-byte writes into a u32 bitmap.
// Warp w accumulates 8 proposals (p = 8w+j) over all 256 features:
// lane l holds feats [4l,4l+4) and [128+4l,128+4l+4) per proposal.
// ---------------------------------------------------------------------------
__global__ __launch_bounds__(256, 2)
void pool_kernel(const float* __restrict__ proposals,
                 const float* __restrict__ xyz,
                 const float* __restrict__ feats)
{
    const int chunk = blockIdx.x;
    const int pbase = blockIdx.y * PG;
    const int tid   = threadIdx.x;
    const int w     = tid >> 5;
    const int l     = tid & 31;
    const int pm    = tid & 63;   // proposal this thread masks
    const int q     = tid >> 6;   // point sub-range [8q, 8q+8)

    __shared__ float4   sf[TILE][64];       // 32 KB: [point][float4 of 256 feats]
    __shared__ float    sxyz[TILE * 3];
    __shared__ unsigned smask[PG];          // per-proposal 32-bit point bitmap
    __shared__ float    sb[PG * 6];         // lo/hi bounds per proposal
    __shared__ float    scnt[4 * PG];

    // Box bounds, bit-exact vs reference (no FMA contraction).
    if (tid < PG) {
        const float* pr = proposals + (size_t)(pbase + tid) * 6;
        const float cx = pr[0], cy = pr[1], cz = pr[2];
        const float hx = __fmul_rn(pr[3], 0.5f);
        const float hy = __fmul_rn(pr[4], 0.5f);
        const float hz = __fmul_rn(pr[5], 0.5f);
        sb[tid * 6 + 0] = __fsub_rn(cx, hx);
        sb[tid * 6 + 1] = __fadd_rn(cx, hx);
        sb[tid * 6 + 2] = __fsub_rn(cy, hy);
        sb[tid * 6 + 3] = __fadd_rn(cy, hy);
        sb[tid * 6 + 4] = __fsub_rn(cz, hz);
        sb[tid * 6 + 5] = __fadd_rn(cz, hz);
    }
    __syncthreads();

    const float alox = sb[pm * 6 + 0], ahix = sb[pm * 6 + 1];
    const float aloy = sb[pm * 6 + 2], ahiy = sb[pm * 6 + 3];
    const float aloz = sb[pm * 6 + 4], ahiz = sb[pm * 6 + 5];

    float4 accA[8], accB[8];
#pragma unroll
    for (int j = 0; j < 8; j++) {
        accA[j] = make_float4(0.f, 0.f, 0.f, 0.f);
        accB[j] = make_float4(0.f, 0.f, 0.f, 0.f);
    }
    float cnt = 0.f;

    const int base = chunk * CHUNK;
    const int nPts = (NPTS - base < CHUNK) ? (NPTS - base) : CHUNK;
    const float4* gf = reinterpret_cast<const float4*>(feats);

    for (int t0 = 0; t0 < nPts; t0 += TILE) {
        const int tn = (nPts - t0 < TILE) ? (nPts - t0) : TILE;

        __syncthreads();   // previous tile fully consumed

        // Stage xyz (pad out-of-range points with 2.0f -> outside every box)
        if (tid < TILE * 3) {
            const bool v = (tid / 3) < tn;
            sxyz[tid] = v ? xyz[(size_t)(base + t0) * 3 + tid] : 2.0f;
        }
        // Stage feature rows (coalesced: 64 consecutive float4 = one 1KB row)
#pragma unroll
        for (int r = 0; r < 8; r++) {
            const int j = tid + r * 256;
            const int i = j >> 6, f = j & 63;
            if (i < tn) sf[i][f] = gf[(size_t)(base + t0 + i) * 64 + f];
        }
        __syncthreads();

        // Build masks: bits [8q, 8q+8) of proposal pm's bitmap
        {
            unsigned mb = 0;
#pragma unroll
            for (int k = 0; k < 8; k++) {
                const int i = q * 8 + k;
                const float x = sxyz[3 * i], y = sxyz[3 * i + 1], z = sxyz[3 * i + 2];
                const bool in = (x >= alox) & (x <= ahix) &
                                (y >= aloy) & (y <= ahiy) &
                                (z >= aloz) & (z <= ahiz);
                mb |= ((unsigned)in) << i;
            }
            reinterpret_cast<unsigned char*>(smask)[pm * 4 + q] =
                (unsigned char)(mb >> (q * 8));
            cnt += (float)__popc(mb);
        }
        __syncthreads();

        // Accumulate: warp-uniform bitmap scan, register accumulator
#pragma unroll
        for (int j = 0; j < 8; j++) {
            unsigned m = smask[(w << 3) + j];
            while (m) {
                const int i = __ffs(m) - 1;
                m &= m - 1;
                const float4 a = sf[i][l];
                const float4 b = sf[i][l + 32];
                accA[j].x += a.x; accA[j].y += a.y; accA[j].z += a.z; accA[j].w += a.w;
                accB[j].x += b.x; accB[j].y += b.y; accB[j].z += b.z; accB[j].w += b.w;
            }
        }
    }

    // Write partial sums (coalesced 512B bursts)
#pragma unroll
    for (int j = 0; j < 8; j++) {
        const int p = (w << 3) + j;
        float4* row = reinterpret_cast<float4*>(&g_partial[chunk][pbase + p][0]);
        row[l]      = accA[j];
        row[l + 32] = accB[j];
    }
    scnt[q * PG + pm] = cnt;
    __syncthreads();
    if (tid < PG)
        g_pcounts[chunk][pbase + tid] =
            scnt[tid] + scnt[PG + tid] + scnt[2 * PG + tid] + scnt[3 * PG + tid];
}

// ---------------------------------------------------------------------------
// Kernel 2: reduce partials -> roi feats -> cls/obj logits.
// grid = 256 (one block per proposal), block = 256 threads.
// ---------------------------------------------------------------------------
__global__ __launch_bounds__(256)
void reduce_kernel(const float* __restrict__ W_cls, const float* __restrict__ b_cls,
                   const float* __restrict__ W_obj, const float* __restrict__ b_obj)
{
    const int p = blockIdx.x;
    const int tid = threadIdx.x;

    __shared__ float roi[RFEAT];
    __shared__ float sc[64];

    // Feature sum across chunks (coalesced: tid spans one 1KB row)
    float s = 0.f;
#pragma unroll 2
    for (int c = 0; c < NCHUNK; c++) s += g_partial[c][p][tid];

    // Count reduction
    float cv = (tid < NCHUNK) ? g_pcounts[tid][p] : 0.f;
#pragma unroll
    for (int o = 16; o > 0; o >>= 1) cv += __shfl_down_sync(0xffffffffu, cv, o);
    if ((tid & 31) == 0) sc[tid >> 5] = cv;
    __syncthreads();
    if (tid == 0) {
        float t = 0.f;
        for (int i = 0; i < 8; i++) t += sc[i];
        sc[0] = 1.0f / fmaxf(t, 1.0f);
    }
    __syncthreads();
    roi[tid] = s * sc[0];
    __syncthreads();

    // Logits: 42 dot products of length 256
    if (tid < 2 * CO) {
        const bool isobj = tid >= CO;
        const int  j     = isobj ? tid - CO : tid;
        const float* Wm  = isobj ? W_obj : W_cls;
        float a = isobj ? b_obj[j] : b_cls[j];
#pragma unroll 8
        for (int f = 0; f < RFEAT; f++) a += roi[f] * Wm[f * CO + j];
        (isobj ? g_obj : g_cls)[p * CO + j] = a;
    }
}

// ---------------------------------------------------------------------------
// Kernel 3: softmaxes + product. 1 block, 256 threads (thread = proposal row).
// ---------------------------------------------------------------------------
__global__ __launch_bounds__(256)
void softmax_kernel(float* __restrict__ out)
{
    const int tid = threadIdx.x;
    __shared__ float sobj[PPROP * CO];   // 21 KB
    __shared__ float cmax[CO], csum[CO];

    for (int e = tid; e < PPROP * CO; e += 256) sobj[e] = g_obj[e];
    __syncthreads();

    // obj column stats (axis=0)
    if (tid < CO) {
        float m = -3.4e38f;
        for (int p = 0; p < PPROP; p++) m = fmaxf(m, sobj[p * CO + tid]);
        float s = 0.f;
        for (int p = 0; p < PPROP; p++) s += expf(sobj[p * CO + tid] - m);
        cmax[tid] = m;
        csum[tid] = s;
    }

    // cls row softmax (axis=1)
    float lg[CO];
    {
        float m = -3.4e38f;
#pragma unroll
        for (int j = 0; j < CO; j++) { lg[j] = g_cls[tid * CO + j]; m = fmaxf(m, lg[j]); }
        float s = 0.f;
#pragma unroll
        for (int j = 0; j < CO; j++) { lg[j] = expf(lg[j] - m); s += lg[j]; }
        const float invs = 1.0f / s;
#pragma unroll
        for (int j = 0; j < CO; j++) lg[j] *= invs;
    }
    __syncthreads();

#pragma unroll
    for (int j = 0; j < CO; j++) {
        const float op = expf(sobj[tid * CO + j] - cmax[j]) / csum[j];
        out[tid * CO + j] = lg[j] * op;
    }
}

// ---------------------------------------------------------------------------
extern "C" void kernel_launch(void* const* d_in, const int* in_sizes, int n_in,
                              void* d_out, int out_size)
{
    const float* proposals = (const float*)d_in[0];
    const float* input_xyz = (const float*)d_in[1];
    const float* seg_feats = (const float*)d_in[2];
    const float* W_cls     = (const float*)d_in[3];
    const float* b_cls     = (const float*)d_in[4];
    const float* W_obj     = (const float*)d_in[5];
    const float* b_obj     = (const float*)d_in[6];
    float* out = (float*)d_out;

    (void)in_sizes; (void)n_in; (void)out_size;

    pool_kernel<<<dim3(NCHUNK, 4), 256>>>(proposals, input_xyz, seg_feats);
    reduce_kernel<<<PPROP, 256>>>(W_cls, b_cls, W_obj, b_obj);
    softmax_kernel<<<1, 256>>>(out);
}

// round 4
// speedup vs baseline: 2.0469x; 1.5233x over previous
#include <cuda_runtime.h>
#include <cstdint>

#define NPTS   100000
#define PPROP  256
#define RFEAT  256
#define CO     21
#define NCHUNK 74
#define CHUNK  1352      // 74*1352 = 100048 >= 100000
#define CPAD   1408      // padded chunk (44 u32 words of mask bits)
#define NWORD  44        // mask words per proposal
#define TILE   16        // points per feature tile
#define PG     64        // proposals per block

// Scratch (__device__ globals: allocation-free rule)
__device__ float g_partial[NCHUNK][PPROP][RFEAT];   // 19.4 MB
__device__ float g_pcounts[NCHUNK][PPROP];
__device__ float g_cls[PPROP * CO];
__device__ float g_obj[PPROP * CO];

__device__ __forceinline__ void cp16(uint32_t saddr, const void* gptr) {
    asm volatile("cp.async.cg.shared.global [%0], [%1], 16;\n"
                 :: "r"(saddr), "l"(gptr));
}
__device__ __forceinline__ void cp_commit() {
    asm volatile("cp.async.commit_group;\n");
}
__device__ __forceinline__ void cp_wait1() {
    asm volatile("cp.async.wait_group 1;\n");
}

// ---------------------------------------------------------------------------
// Kernel 1: sparse ROI pooling, pipelined.
// grid = (74 chunks, 4 proposal-groups), block = 256, 2 CTAs/SM.
// Phase A: stage chunk xyz -> build full-chunk 1408-bit mask per proposal
//          (thread t: proposal t&63, points [352q, 352q+352), q = t>>6).
// Phase B: double-buffered cp.async feature tiles (16 pts x 256 feats);
//          warp w scans precomputed bitmaps for its 8 proposals and
//          accumulates all 256 feats in registers.
// ---------------------------------------------------------------------------
__global__ __launch_bounds__(256, 2)
void pool_kernel(const float* __restrict__ proposals,
                 const float* __restrict__ xyz,
                 const float* __restrict__ feats)
{
    const int chunk = blockIdx.x;
    const int pbase = blockIdx.y * PG;
    const int tid   = threadIdx.x;
    const int w     = tid >> 5;
    const int l     = tid & 31;
    const int pm    = tid & 63;   // proposal this thread masks
    const int q     = tid >> 6;   // point quarter [352q, 352q+352)

    __shared__ union {
        float4 sf[2][TILE][64];   // 32 KB feature double-buffer
        float  sxyz[CPAD * 3];    // 16.9 KB xyz staging (phase A only)
    } u;
    __shared__ unsigned smask[PG][NWORD];   // 11.3 KB bitmaps
    __shared__ float    scnt[4 * PG];

    const int base = chunk * CHUNK;
    const int nPts = (NPTS - base < CHUNK) ? (NPTS - base) : CHUNK;

    // ---- Phase A: stage xyz (pad with 2.0 -> outside every box) ----
    {
        const float* gx = xyz + (size_t)base * 3;
        const int nf = nPts * 3;
#pragma unroll
        for (int k = 0; k < 17; k++) {
            const int j = tid + k * 256;
            if (j < CPAD * 3) u.sxyz[j] = (j < nf) ? gx[j] : 2.0f;
        }
    }

    // Box bounds, bit-exact vs reference (no FMA contraction).
    float alox, ahix, aloy, ahiy, aloz, ahiz;
    {
        const float* pr = proposals + (size_t)(pbase + pm) * 6;
        const float cx = pr[0], cy = pr[1], cz = pr[2];
        const float hx = __fmul_rn(pr[3], 0.5f);
        const float hy = __fmul_rn(pr[4], 0.5f);
        const float hz = __fmul_rn(pr[5], 0.5f);
        alox = __fsub_rn(cx, hx);  ahix = __fadd_rn(cx, hx);
        aloy = __fsub_rn(cy, hy);  ahiy = __fadd_rn(cy, hy);
        aloz = __fsub_rn(cz, hz);  ahiz = __fadd_rn(cz, hz);
    }
    __syncthreads();

    // ---- Build masks: 11 words of 32 tests each ----
    {
        float cnt = 0.f;
#pragma unroll
        for (int wd = 0; wd < 11; wd++) {
            unsigned bits = 0;
#pragma unroll
            for (int k = 0; k < 32; k++) {
                const int i = q * 352 + wd * 32 + k;
                const float x = u.sxyz[3 * i];
                const float y = u.sxyz[3 * i + 1];
                const float z = u.sxyz[3 * i + 2];
                const bool in = (x >= alox) & (x <= ahix) &
                                (y >= aloy) & (y <= ahiy) &
                                (z >= aloz) & (z <= ahiz);
                bits |= ((unsigned)in) << k;
            }
            smask[pm][q * 11 + wd] = bits;
            cnt += (float)__popc(bits);
        }
        scnt[q * PG + pm] = cnt;
    }
    __syncthreads();   // masks done; xyz area now reusable for features

    if (tid < PG)
        g_pcounts[chunk][pbase + tid] =
            scnt[tid] + scnt[PG + tid] + scnt[2 * PG + tid] + scnt[3 * PG + tid];

    // ---- Phase B: pipelined feature accumulation ----
    float4 accA[8], accB[8];
#pragma unroll
    for (int j = 0; j < 8; j++) {
        accA[j] = make_float4(0.f, 0.f, 0.f, 0.f);
        accB[j] = make_float4(0.f, 0.f, 0.f, 0.f);
    }

    const float4* gf = reinterpret_cast<const float4*>(feats);
    const int ntiles = (nPts + TILE - 1) / TILE;

    // per-thread cp.async slots: j = tid + 256k -> point i = j>>6, f4 = j&63
    const int ci = tid >> 6;          // base point within tile (0..3)
    const int cf = tid & 63;          // float4 column

    auto issue = [&](int t, int buf) {
        const int t0 = t * TILE;
#pragma unroll
        for (int k = 0; k < 4; k++) {
            const int i = ci + k * 4;
            const int pt = t0 + i;
            if (pt < nPts) {
                uint32_t s = (uint32_t)__cvta_generic_to_shared(&u.sf[buf][i][cf]);
                cp16(s, gf + (size_t)(base + pt) * 64 + cf);
            }
        }
        cp_commit();
    };

    issue(0, 0);
    for (int t = 0; t < ntiles; t++) {
        if (t + 1 < ntiles) issue(t + 1, (t + 1) & 1);
        else cp_commit();   // keep group count aligned
        cp_wait1();
        __syncthreads();    // buf t&1 visible to all

        const int buf = t & 1;
        const unsigned sh = (t & 1) << 4;
        const int wd = t >> 1;
#pragma unroll
        for (int j = 0; j < 8; j++) {
            unsigned m = (smask[(w << 3) + j][wd] >> sh) & 0xFFFFu;
            while (m) {
                const int i = __ffs(m) - 1;
                m &= m - 1;
                const float4 a = u.sf[buf][i][l];
                const float4 b = u.sf[buf][i][l + 32];
                accA[j].x += a.x; accA[j].y += a.y; accA[j].z += a.z; accA[j].w += a.w;
                accB[j].x += b.x; accB[j].y += b.y; accB[j].z += b.z; accB[j].w += b.w;
            }
        }
        __syncthreads();    // all consumed before buf is overwritten (t+2)
    }

    // Write partial sums (coalesced 512B bursts)
#pragma unroll
    for (int j = 0; j < 8; j++) {
        const int p = (w << 3) + j;
        float4* row = reinterpret_cast<float4*>(&g_partial[chunk][pbase + p][0]);
        row[l]      = accA[j];
        row[l + 32] = accB[j];
    }
}

// ---------------------------------------------------------------------------
// Kernel 2: reduce partials -> roi -> logits (warp-parallel dots).
// grid = 256 (block per proposal), block = 256.
// ---------------------------------------------------------------------------
__global__ __launch_bounds__(256)
void reduce_kernel(const float* __restrict__ W_cls, const float* __restrict__ b_cls,
                   const float* __restrict__ W_obj, const float* __restrict__ b_obj)
{
    const int p   = blockIdx.x;
    const int tid = threadIdx.x;
    const int w   = tid >> 5;
    const int l   = tid & 31;

    __shared__ float roi[RFEAT];
    __shared__ float sc[8];

    // Feature sum across chunks (coalesced rows)
    float s = 0.f;
#pragma unroll 4
    for (int c = 0; c < NCHUNK; c++) s += g_partial[c][p][tid];

    // Count reduction
    float cv = (tid < NCHUNK) ? g_pcounts[tid][p] : 0.f;
#pragma unroll
    for (int o = 16; o > 0; o >>= 1) cv += __shfl_down_sync(0xffffffffu, cv, o);
    if (l == 0) sc[w] = cv;
    __syncthreads();
    if (tid == 0) {
        float t = 0.f;
#pragma unroll
        for (int i = 0; i < 8; i++) t += sc[i];
        sc[0] = 1.0f / fmaxf(t, 1.0f);
    }
    __syncthreads();
    roi[tid] = s * sc[0];
    __syncthreads();

    // Logits: 42 warp-reduced dot products of length 256
    for (int o = w; o < 2 * CO; o += 8) {
        const bool isobj = o >= CO;
        const int  j     = isobj ? o - CO : o;
        const float* Wm  = isobj ? W_obj : W_cls;
        float a = 0.f;
#pragma unroll
        for (int f = l; f < RFEAT; f += 32) a += roi[f] * Wm[f * CO + j];
#pragma unroll
        for (int off = 16; off > 0; off >>= 1)
            a += __shfl_xor_sync(0xffffffffu, a, off);
        if (l == 0)
            (isobj ? g_obj : g_cls)[p * CO + j] = a + (isobj ? b_obj[j] : b_cls[j]);
    }
}

// ---------------------------------------------------------------------------
// Kernel 3: softmaxes + product. 1 block, 256 threads (thread = proposal row).
// ---------------------------------------------------------------------------
__global__ __launch_bounds__(256)
void softmax_kernel(float* __restrict__ out)
{
    const int tid = threadIdx.x;
    __shared__ float sobj[PPROP * CO];   // 21 KB
    __shared__ float cmax[CO], csum[CO];

    for (int e = tid; e < PPROP * CO; e += 256) sobj[e] = g_obj[e];
    __syncthreads();

    if (tid < CO) {
        float m = -3.4e38f;
        for (int p = 0; p < PPROP; p++) m = fmaxf(m, sobj[p * CO + tid]);
        float s = 0.f;
        for (int p = 0; p < PPROP; p++) s += expf(sobj[p * CO + tid] - m);
        cmax[tid] = m;
        csum[tid] = s;
    }

    float lg[CO];
    {
        float m = -3.4e38f;
#pragma unroll
        for (int j = 0; j < CO; j++) { lg[j] = g_cls[tid * CO + j]; m = fmaxf(m, lg[j]); }
        float s = 0.f;
#pragma unroll
        for (int j = 0; j < CO; j++) { lg[j] = expf(lg[j] - m); s += lg[j]; }
        const float invs = 1.0f / s;
#pragma unroll
        for (int j = 0; j < CO; j++) lg[j] *= invs;
    }
    __syncthreads();

#pragma unroll
    for (int j = 0; j < CO; j++) {
        const float op = expf(sobj[tid * CO + j] - cmax[j]) / csum[j];
        out[tid * CO + j] = lg[j] * op;
    }
}

// ---------------------------------------------------------------------------
extern "C" void kernel_launch(void* const* d_in, const int* in_sizes, int n_in,
                              void* d_out, int out_size)
{
    const float* proposals = (const float*)d_in[0];
    const float* input_xyz = (const float*)d_in[1];
    const float* seg_feats = (const float*)d_in[2];
    const float* W_cls     = (const float*)d_in[3];
    const float* b_cls     = (const float*)d_in[4];
    const float* W_obj     = (const float*)d_in[5];
    const float* b_obj     = (const float*)d_in[6];
    float* out = (float*)d_out;

    (void)in_sizes; (void)n_in; (void)out_size;

    pool_kernel<<<dim3(NCHUNK, 4), 256>>>(proposals, input_xyz, seg_feats);
    reduce_kernel<<<PPROP, 256>>>(W_cls, b_cls, W_obj, b_obj);
    softmax_kernel<<<1, 256>>>(out);
}

// round 5
// speedup vs baseline: 2.2607x; 1.1045x over previous
#include <cuda_runtime.h>
#include <cstdint>

#define NPTS   100000
#define PPROP  256
#define RFEAT  256
#define CO     21
#define NCHUNK 74
#define CHUNK  1352      // 74*1352 = 100048 >= 100000
#define CPAD   1536      // padded chunk (48 u32 mask words)
#define NWORD  48
#define TILE   32        // points per feature tile (= one mask word)
#define PG     64        // proposals per block

// Scratch (__device__ globals: allocation-free rule)
__device__ float g_partial[NCHUNK][PPROP][RFEAT];   // 19.4 MB
__device__ float g_pcounts[NCHUNK][PPROP];
__device__ float g_cls[PPROP * CO];
__device__ float g_obj[PPROP * CO];

__device__ __forceinline__ void cp16(uint32_t saddr, const void* gptr) {
    asm volatile("cp.async.cg.shared.global [%0], [%1], 16;\n"
                 :: "r"(saddr), "l"(gptr));
}
__device__ __forceinline__ void cp_commit() {
    asm volatile("cp.async.commit_group;\n");
}
__device__ __forceinline__ void cp_wait1() {
    asm volatile("cp.async.wait_group 1;\n");
}
#define ADD_F32X2(out, a, b) \
    asm("add.rn.f32x2 %0, %1, %2;" : "=l"(out) : "l"(a), "l"(b))

struct PoolSmem {
    union {
        float4 sf[2][TILE][64];   // 64 KB feature double-buffer (f32)
        float  sxyz[CPAD * 3];    // 18 KB xyz staging (phase A only)
    } u;
    unsigned smask[PG][NWORD];    // 12 KB bitmaps
    float    scnt[8][PG];         // 2 KB
};
#define POOL_SMEM_BYTES ((int)sizeof(PoolSmem))

// ---------------------------------------------------------------------------
// Kernel 1: sparse ROI pooling.
// grid = (74 chunks, 4 proposal-groups), block = 512, 2 CTAs/SM (32 warps).
// Phase A: stage chunk xyz -> full-chunk 1536-bit mask per proposal
//          (thread t: proposal t&63, points [192q, 192q+192), q = t>>6).
// Phase B: double-buffered cp.async tiles (32 pts x 256 f32 feats);
//          warp w = (wp = w&7, wh = w>>3): scans proposals [8wp,8wp+8) and
//          accumulates feature half wh in registers via packed f32x2 adds.
// ---------------------------------------------------------------------------
__global__ __launch_bounds__(512, 2)
void pool_kernel(const float* __restrict__ proposals,
                 const float* __restrict__ xyz,
                 const float* __restrict__ feats)
{
    extern __shared__ char smem_raw[];
    PoolSmem* s = reinterpret_cast<PoolSmem*>(smem_raw);

    const int chunk = blockIdx.x;
    const int pbase = blockIdx.y * PG;
    const int tid   = threadIdx.x;
    const int w     = tid >> 5;
    const int l     = tid & 31;
    const int wp    = w & 7;      // proposal octet
    const int wh    = w >> 3;     // feature half
    const int pm    = tid & 63;   // proposal this thread masks
    const int q     = tid >> 6;   // point range [192q, 192q+192)

    const int base = chunk * CHUNK;
    const int nPts = (NPTS - base < CHUNK) ? (NPTS - base) : CHUNK;

    // ---- Phase A: stage xyz (pad with 2.0 -> outside every box) ----
    {
        const float* gx = xyz + (size_t)base * 3;
        const int nf = nPts * 3;
#pragma unroll
        for (int k = 0; k < 9; k++) {               // 9*512 = 4608 = CPAD*3
            const int j = tid + k * 512;
            s->u.sxyz[j] = (j < nf) ? gx[j] : 2.0f;
        }
    }

    // Box bounds, bit-exact vs reference (no FMA contraction).
    float alox, ahix, aloy, ahiy, aloz, ahiz;
    {
        const float* pr = proposals + (size_t)(pbase + pm) * 6;
        const float cx = pr[0], cy = pr[1], cz = pr[2];
        const float hx = __fmul_rn(pr[3], 0.5f);
        const float hy = __fmul_rn(pr[4], 0.5f);
        const float hz = __fmul_rn(pr[5], 0.5f);
        alox = __fsub_rn(cx, hx);  ahix = __fadd_rn(cx, hx);
        aloy = __fsub_rn(cy, hy);  ahiy = __fadd_rn(cy, hy);
        aloz = __fsub_rn(cz, hz);  ahiz = __fadd_rn(cz, hz);
    }
    __syncthreads();

    // ---- Build masks: 6 words of 32 tests each ----
    {
        float cnt = 0.f;
#pragma unroll
        for (int wd = 0; wd < 6; wd++) {
            unsigned bits = 0;
#pragma unroll
            for (int k = 0; k < 32; k++) {
                const int i = q * 192 + wd * 32 + k;
                const float x = s->u.sxyz[3 * i];
                const float y = s->u.sxyz[3 * i + 1];
                const float z = s->u.sxyz[3 * i + 2];
                const bool in = (x >= alox) & (x <= ahix) &
                                (y >= aloy) & (y <= ahiy) &
                                (z >= aloz) & (z <= ahiz);
                bits |= ((unsigned)in) << k;
            }
            s->smask[pm][q * 6 + wd] = bits;
            cnt += (float)__popc(bits);
        }
        s->scnt[q][pm] = cnt;
    }
    __syncthreads();   // masks done; xyz area now reusable for features

    if (tid < PG) {
        float c = 0.f;
#pragma unroll
        for (int k = 0; k < 8; k++) c += s->scnt[k][tid];
        g_pcounts[chunk][pbase + tid] = c;
    }

    // ---- Phase B: pipelined feature accumulation ----
    ulonglong2 acc2[8];
#pragma unroll
    for (int j = 0; j < 8; j++) { acc2[j].x = 0ull; acc2[j].y = 0ull; }

    const float4* gf = reinterpret_cast<const float4*>(feats);
    const int ntiles = (nPts + TILE - 1) / TILE;

    const int ci = tid >> 6;   // base point within tile (0..7)
    const int cf = tid & 63;   // float4 column

    auto issue = [&](int t, int buf) {
        const int t0 = t * TILE;
#pragma unroll
        for (int k = 0; k < 4; k++) {
            const int i = ci + 8 * k;
            const int pt = t0 + i;
            if (pt < nPts) {
                uint32_t sa = (uint32_t)__cvta_generic_to_shared(&s->u.sf[buf][i][cf]);
                cp16(sa, gf + (size_t)(base + pt) * 64 + cf);
            }
        }
        cp_commit();
    };

    issue(0, 0);
    for (int t = 0; t < ntiles; t++) {
        if (t + 1 < ntiles) issue(t + 1, (t + 1) & 1);
        else cp_commit();   // keep group count aligned
        cp_wait1();
        __syncthreads();    // buf t&1 visible to all

        const int buf = t & 1;
        const int fc  = (wh << 5) + l;
#pragma unroll
        for (int j = 0; j < 8; j++) {
            unsigned m = s->smask[(wp << 3) + j][t];
            while (m) {
                const int i = __ffs(m) - 1;
                m &= m - 1;
                const ulonglong2 v =
                    *reinterpret_cast<const ulonglong2*>(&s->u.sf[buf][i][fc]);
                ADD_F32X2(acc2[j].x, acc2[j].x, v.x);
                ADD_F32X2(acc2[j].y, acc2[j].y, v.y);
            }
        }
        __syncthreads();    // all consumed before buf is overwritten (t+2)
    }

    // Write partial sums (coalesced 512B bursts per half)
#pragma unroll
    for (int j = 0; j < 8; j++) {
        const int p = (wp << 3) + j;
        ulonglong2* row =
            reinterpret_cast<ulonglong2*>(&g_partial[chunk][pbase + p][0]);
        row[(wh << 5) + l] = acc2[j];
    }
}

// ---------------------------------------------------------------------------
// Kernel 2: reduce partials -> roi -> logits (warp-parallel dots).
// grid = 256 (block per proposal), block = 256.
// ---------------------------------------------------------------------------
__global__ __launch_bounds__(256)
void reduce_kernel(const float* __restrict__ W_cls, const float* __restrict__ b_cls,
                   const float* __restrict__ W_obj, const float* __restrict__ b_obj)
{
    const int p   = blockIdx.x;
    const int tid = threadIdx.x;
    const int w   = tid >> 5;
    const int l   = tid & 31;

    __shared__ float roi[RFEAT];
    __shared__ float sc[8];

    // Feature sum across chunks (coalesced rows)
    float sum = 0.f;
#pragma unroll 4
    for (int c = 0; c < NCHUNK; c++) sum += g_partial[c][p][tid];

    // Count reduction
    float cv = (tid < NCHUNK) ? g_pcounts[tid][p] : 0.f;
#pragma unroll
    for (int o = 16; o > 0; o >>= 1) cv += __shfl_down_sync(0xffffffffu, cv, o);
    if (l == 0) sc[w] = cv;
    __syncthreads();
    if (tid == 0) {
        float t = 0.f;
#pragma unroll
        for (int i = 0; i < 8; i++) t += sc[i];
        sc[0] = 1.0f / fmaxf(t, 1.0f);
    }
    __syncthreads();
    roi[tid] = sum * sc[0];
    __syncthreads();

    // Logits: 42 warp-reduced dot products of length 256
    for (int o = w; o < 2 * CO; o += 8) {
        const bool isobj = o >= CO;
        const int  j     = isobj ? o - CO : o;
        const float* Wm  = isobj ? W_obj : W_cls;
        float a = 0.f;
#pragma unroll
        for (int f = l; f < RFEAT; f += 32) a += roi[f] * Wm[f * CO + j];
#pragma unroll
        for (int off = 16; off > 0; off >>= 1)
            a += __shfl_xor_sync(0xffffffffu, a, off);
        if (l == 0)
            (isobj ? g_obj : g_cls)[p * CO + j] = a + (isobj ? b_obj[j] : b_cls[j]);
    }
}

// ---------------------------------------------------------------------------
// Kernel 3: softmaxes + product. 1 block, 256 threads.
// obj column stats parallelized 12 threads per column.
// ---------------------------------------------------------------------------
__global__ __launch_bounds__(256)
void softmax_kernel(float* __restrict__ out)
{
    const int tid = threadIdx.x;
    __shared__ float sobj[PPROP * CO];   // 21 KB
    __shared__ float red[CO][12];
    __shared__ float cmax[CO], cinv[CO];

    for (int e = tid; e < PPROP * CO; e += 256) sobj[e] = g_obj[e];
    __syncthreads();

    const int c = tid / 12;   // column (0..20) for tid < 252
    const int r = tid % 12;

    // column max
    if (tid < 252) {
        float m = -3.4e38f;
        for (int p = r; p < PPROP; p += 12) m = fmaxf(m, sobj[p * CO + c]);
        red[c][r] = m;
    }
    __syncthreads();
    if (tid < CO) {
        float m = red[tid][0];
#pragma unroll
        for (int k = 1; k < 12; k++) m = fmaxf(m, red[tid][k]);
        cmax[tid] = m;
    }
    __syncthreads();
    // column exp-sum (write exp back in place)
    if (tid < 252) {
        const float m = cmax[c];
        float sm = 0.f;
        for (int p = r; p < PPROP; p += 12) {
            const float e = expf(sobj[p * CO + c] - m);
            sobj[p * CO + c] = e;
            sm += e;
        }
        red[c][r] = sm;
    }
    __syncthreads();
    if (tid < CO) {
        float sm = 0.f;
#pragma unroll
        for (int k = 0; k < 12; k++) sm += red[tid][k];
        cinv[tid] = 1.0f / sm;
    }

    // cls row softmax (axis=1), independent of column pass
    float lg[CO];
    {
        float m = -3.4e38f;
#pragma unroll
        for (int j = 0; j < CO; j++) { lg[j] = g_cls[tid * CO + j]; m = fmaxf(m, lg[j]); }
        float sm = 0.f;
#pragma unroll
        for (int j = 0; j < CO; j++) { lg[j] = expf(lg[j] - m); sm += lg[j]; }
        const float invs = 1.0f / sm;
#pragma unroll
        for (int j = 0; j < CO; j++) lg[j] *= invs;
    }
    __syncthreads();

#pragma unroll
    for (int j = 0; j < CO; j++)
        out[tid * CO + j] = lg[j] * sobj[tid * CO + j] * cinv[j];
}

// ---------------------------------------------------------------------------
extern "C" void kernel_launch(void* const* d_in, const int* in_sizes, int n_in,
                              void* d_out, int out_size)
{
    const float* proposals = (const float*)d_in[0];
    const float* input_xyz = (const float*)d_in[1];
    const float* seg_feats = (const float*)d_in[2];
    const float* W_cls     = (const float*)d_in[3];
    const float* b_cls     = (const float*)d_in[4];
    const float* W_obj     = (const float*)d_in[5];
    const float* b_obj     = (const float*)d_in[6];
    float* out = (float*)d_out;

    (void)in_sizes; (void)n_in; (void)out_size;

    cudaFuncSetAttribute(pool_kernel,
                         cudaFuncAttributeMaxDynamicSharedMemorySize,
                         POOL_SMEM_BYTES);
    pool_kernel<<<dim3(NCHUNK, 4), 512, POOL_SMEM_BYTES>>>(proposals, input_xyz, seg_feats);
    reduce_kernel<<<PPROP, 256>>>(W_cls, b_cls, W_obj, b_obj);
    softmax_kernel<<<1, 256>>>(out);
}

// round 6
// speedup vs baseline: 2.6337x; 1.1650x over previous
#include <cuda_runtime.h>
#include <cstdint>

#define NPTS   100000
#define PPROP  256
#define RFEAT  256
#define CO     21
#define NCHUNK 74
#define CHUNK  1352      // 74*1352 = 100048 >= 100000
#define CPAD   1536      // padded chunk (48 u32 mask words)
#define NWORD  48
#define TILE   32        // points per feature tile (= one mask word)
#define PG     64        // proposals per block

// Scratch (__device__ globals: allocation-free rule)
__device__ float g_partial[NCHUNK][PPROP][RFEAT];   // 19.4 MB
__device__ float g_pcounts[NCHUNK][PPROP];
__device__ float g_cls[PPROP * CO];
__device__ float g_obj[PPROP * CO];

__device__ __forceinline__ void cp16(uint32_t saddr, const void* gptr) {
    asm volatile("cp.async.cg.shared.global [%0], [%1], 16;\n"
                 :: "r"(saddr), "l"(gptr));
}
__device__ __forceinline__ void cp_commit() {
    asm volatile("cp.async.commit_group;\n");
}
__device__ __forceinline__ void cp_wait1() {
    asm volatile("cp.async.wait_group 1;\n");
}
#define ADD_F32X2(out, a, b) \
    asm("add.rn.f32x2 %0, %1, %2;" : "=l"(out) : "l"(a), "l"(b))

struct PoolSmem {
    union {
        float4 sf[2][TILE][64];   // 64 KB feature double-buffer (f32)
        float  sxyz[CPAD * 3];    // 18 KB xyz staging (phase A only)
    } u;
    unsigned smask[PG][NWORD];    // 12 KB bitmaps
    float    scnt[8][PG];         // 2 KB
};
#define POOL_SMEM_BYTES ((int)sizeof(PoolSmem))

// ---------------------------------------------------------------------------
// Kernel 1: sparse ROI pooling.
// grid = (74 chunks, 4 proposal-groups), block = 512, 2 CTAs/SM (32 warps).
// Phase A: stage chunk xyz -> full-chunk 1536-bit mask per proposal
//          (thread t: proposal t&63, points [192q, 192q+192), q = t>>6).
// Phase B: double-buffered cp.async tiles (32 pts x 256 f32 feats);
//          warp w owns proposals [4w, 4w+4) and ALL 256 features:
//          each mask word scanned exactly once; per membership the warp does
//          2x LDS.128 + 4x packed f32x2 adds into register accumulators.
// ---------------------------------------------------------------------------
__global__ __launch_bounds__(512, 2)
void pool_kernel(const float* __restrict__ proposals,
                 const float* __restrict__ xyz,
                 const float* __restrict__ feats)
{
    extern __shared__ char smem_raw[];
    PoolSmem* s = reinterpret_cast<PoolSmem*>(smem_raw);

    const int chunk = blockIdx.x;
    const int pbase = blockIdx.y * PG;
    const int tid   = threadIdx.x;
    const int w     = tid >> 5;
    const int l     = tid & 31;
    const int pm    = tid & 63;   // proposal this thread masks
    const int q     = tid >> 6;   // point range [192q, 192q+192)

    const int base = chunk * CHUNK;
    const int nPts = (NPTS - base < CHUNK) ? (NPTS - base) : CHUNK;

    // ---- Phase A: stage xyz (pad with 2.0 -> outside every box) ----
    {
        const float* gx = xyz + (size_t)base * 3;
        const int nf = nPts * 3;
#pragma unroll
        for (int k = 0; k < 9; k++) {               // 9*512 = 4608 = CPAD*3
            const int j = tid + k * 512;
            s->u.sxyz[j] = (j < nf) ? gx[j] : 2.0f;
        }
    }

    // Box bounds, bit-exact vs reference (no FMA contraction).
    float alox, ahix, aloy, ahiy, aloz, ahiz;
    {
        const float* pr = proposals + (size_t)(pbase + pm) * 6;
        const float cx = pr[0], cy = pr[1], cz = pr[2];
        const float hx = __fmul_rn(pr[3], 0.5f);
        const float hy = __fmul_rn(pr[4], 0.5f);
        const float hz = __fmul_rn(pr[5], 0.5f);
        alox = __fsub_rn(cx, hx);  ahix = __fadd_rn(cx, hx);
        aloy = __fsub_rn(cy, hy);  ahiy = __fadd_rn(cy, hy);
        aloz = __fsub_rn(cz, hz);  ahiz = __fadd_rn(cz, hz);
    }
    __syncthreads();

    // ---- Build masks: 6 words of 32 tests each ----
    {
        float cnt = 0.f;
#pragma unroll
        for (int wd = 0; wd < 6; wd++) {
            unsigned bits = 0;
#pragma unroll
            for (int k = 0; k < 32; k++) {
                const int i = q * 192 + wd * 32 + k;
                const float x = s->u.sxyz[3 * i];
                const float y = s->u.sxyz[3 * i + 1];
                const float z = s->u.sxyz[3 * i + 2];
                const bool in = (x >= alox) & (x <= ahix) &
                                (y >= aloy) & (y <= ahiy) &
                                (z >= aloz) & (z <= ahiz);
                bits |= ((unsigned)in) << k;
            }
            s->smask[pm][q * 6 + wd] = bits;
            cnt += (float)__popc(bits);
        }
        s->scnt[q][pm] = cnt;
    }
    __syncthreads();   // masks done; xyz area now reusable for features

    if (tid < PG) {
        float c = 0.f;
#pragma unroll
        for (int k = 0; k < 8; k++) c += s->scnt[k][tid];
        g_pcounts[chunk][pbase + tid] = c;
    }

    // ---- Phase B: pipelined feature accumulation ----
    // Warp w owns proposals [4w, 4w+4); lane l holds feats [4l,4l+4) (A) and
    // [128+4l, 128+4l+4) (B) for each.
    ulonglong2 accA[4], accB[4];
#pragma unroll
    for (int j = 0; j < 4; j++) {
        accA[j].x = 0ull; accA[j].y = 0ull;
        accB[j].x = 0ull; accB[j].y = 0ull;
    }

    const float4* gf = reinterpret_cast<const float4*>(feats);
    const int ntiles = (nPts + TILE - 1) / TILE;

    const int ci = tid >> 6;   // base point within tile (0..7)
    const int cf = tid & 63;   // float4 column

    auto issue = [&](int t, int buf) {
        const int t0 = t * TILE;
#pragma unroll
        for (int k = 0; k < 4; k++) {
            const int i = ci + 8 * k;
            const int pt = t0 + i;
            if (pt < nPts) {
                uint32_t sa = (uint32_t)__cvta_generic_to_shared(&s->u.sf[buf][i][cf]);
                cp16(sa, gf + (size_t)(base + pt) * 64 + cf);
            }
        }
        cp_commit();
    };

    issue(0, 0);
    for (int t = 0; t < ntiles; t++) {
        if (t + 1 < ntiles) issue(t + 1, (t + 1) & 1);
        else cp_commit();   // keep group count aligned
        cp_wait1();
        __syncthreads();    // buf t&1 visible to all

        const int buf = t & 1;
#pragma unroll
        for (int j = 0; j < 4; j++) {
            unsigned m = s->smask[(w << 2) + j][t];
            while (m) {
                const int i = __ffs(m) - 1;
                m &= m - 1;
                const ulonglong2 va =
                    *reinterpret_cast<const ulonglong2*>(&s->u.sf[buf][i][l]);
                const ulonglong2 vb =
                    *reinterpret_cast<const ulonglong2*>(&s->u.sf[buf][i][l + 32]);
                ADD_F32X2(accA[j].x, accA[j].x, va.x);
                ADD_F32X2(accA[j].y, accA[j].y, va.y);
                ADD_F32X2(accB[j].x, accB[j].x, vb.x);
                ADD_F32X2(accB[j].y, accB[j].y, vb.y);
            }
        }
        __syncthreads();    // all consumed before buf is overwritten (t+2)
    }

    // Write partial sums (coalesced 512B bursts)
#pragma unroll
    for (int j = 0; j < 4; j++) {
        const int p = (w << 2) + j;
        ulonglong2* row =
            reinterpret_cast<ulonglong2*>(&g_partial[chunk][pbase + p][0]);
        row[l]      = accA[j];
        row[l + 32] = accB[j];
    }
}

// ---------------------------------------------------------------------------
// Kernel 2: reduce partials -> roi -> logits (warp-parallel dots).
// grid = 256 (block per proposal), block = 256.
// Chunk loop fully unrolled with 4 accumulators for deep MLP.
// ---------------------------------------------------------------------------
__global__ __launch_bounds__(256)
void reduce_kernel(const float* __restrict__ W_cls, const float* __restrict__ b_cls,
                   const float* __restrict__ W_obj, const float* __restrict__ b_obj)
{
    const int p   = blockIdx.x;
    const int tid = threadIdx.x;
    const int w   = tid >> 5;
    const int l   = tid & 31;

    __shared__ float roi[RFEAT];
    __shared__ float sc[8];

    // Feature sum across chunks: 4 independent chains, fully unrolled.
    float s0 = 0.f, s1 = 0.f, s2 = 0.f, s3 = 0.f;
#pragma unroll
    for (int c = 0; c < 72; c += 4) {
        s0 += g_partial[c    ][p][tid];
        s1 += g_partial[c + 1][p][tid];
        s2 += g_partial[c + 2][p][tid];
        s3 += g_partial[c + 3][p][tid];
    }
    s0 += g_partial[72][p][tid];
    s1 += g_partial[73][p][tid];
    const float sum = (s0 + s1) + (s2 + s3);

    // Count reduction
    float cv = (tid < NCHUNK) ? g_pcounts[tid][p] : 0.f;
#pragma unroll
    for (int o = 16; o > 0; o >>= 1) cv += __shfl_down_sync(0xffffffffu, cv, o);
    if (l == 0) sc[w] = cv;
    __syncthreads();
    if (tid == 0) {
        float t = 0.f;
#pragma unroll
        for (int i = 0; i < 8; i++) t += sc[i];
        sc[0] = 1.0f / fmaxf(t, 1.0f);
    }
    __syncthreads();
    roi[tid] = sum * sc[0];
    __syncthreads();

    // Logits: 42 warp-reduced dot products of length 256
    for (int o = w; o < 2 * CO; o += 8) {
        const bool isobj = o >= CO;
        const int  j     = isobj ? o - CO : o;
        const float* Wm  = isobj ? W_obj : W_cls;
        float a = 0.f;
#pragma unroll
        for (int f = l; f < RFEAT; f += 32) a += roi[f] * Wm[f * CO + j];
#pragma unroll
        for (int off = 16; off > 0; off >>= 1)
            a += __shfl_xor_sync(0xffffffffu, a, off);
        if (l == 0)
            (isobj ? g_obj : g_cls)[p * CO + j] = a + (isobj ? b_obj[j] : b_cls[j]);
    }
}

// ---------------------------------------------------------------------------
// Kernel 3: softmaxes + product. 1 block, 256 threads.
// obj column stats parallelized 12 threads per column.
// ---------------------------------------------------------------------------
__global__ __launch_bounds__(256)
void softmax_kernel(float* __restrict__ out)
{
    const int tid = threadIdx.x;
    __shared__ float sobj[PPROP * CO];   // 21 KB
    __shared__ float red[CO][12];
    __shared__ float cmax[CO], cinv[CO];

    for (int e = tid; e < PPROP * CO; e += 256) sobj[e] = g_obj[e];
    __syncthreads();

    const int c = tid / 12;   // column (0..20) for tid < 252
    const int r = tid % 12;

    if (tid < 252) {
        float m = -3.4e38f;
        for (int p = r; p < PPROP; p += 12) m = fmaxf(m, sobj[p * CO + c]);
        red[c][r] = m;
    }
    __syncthreads();
    if (tid < CO) {
        float m = red[tid][0];
#pragma unroll
        for (int k = 1; k < 12; k++) m = fmaxf(m, red[tid][k]);
        cmax[tid] = m;
    }
    __syncthreads();
    if (tid < 252) {
        const float m = cmax[c];
        float sm = 0.f;
        for (int p = r; p < PPROP; p += 12) {
            const float e = expf(sobj[p * CO + c] - m);
            sobj[p * CO + c] = e;
            sm += e;
        }
        red[c][r] = sm;
    }
    __syncthreads();
    if (tid < CO) {
        float sm = 0.f;
#pragma unroll
        for (int k = 0; k < 12; k++) sm += red[tid][k];
        cinv[tid] = 1.0f / sm;
    }

    // cls row softmax (axis=1)
    float lg[CO];
    {
        float m = -3.4e38f;
#pragma unroll
        for (int j = 0; j < CO; j++) { lg[j] = g_cls[tid * CO + j]; m = fmaxf(m, lg[j]); }
        float sm = 0.f;
#pragma unroll
        for (int j = 0; j < CO; j++) { lg[j] = expf(lg[j] - m); sm += lg[j]; }
        const float invs = 1.0f / sm;
#pragma unroll
        for (int j = 0; j < CO; j++) lg[j] *= invs;
    }
    __syncthreads();

#pragma unroll
    for (int j = 0; j < CO; j++)
        out[tid * CO + j] = lg[j] * sobj[tid * CO + j] * cinv[j];
}

// ---------------------------------------------------------------------------
extern "C" void kernel_launch(void* const* d_in, const int* in_sizes, int n_in,
                              void* d_out, int out_size)
{
    const float* proposals = (const float*)d_in[0];
    const float* input_xyz = (const float*)d_in[1];
    const float* seg_feats = (const float*)d_in[2];
    const float* W_cls     = (const float*)d_in[3];
    const float* b_cls     = (const float*)d_in[4];
    const float* W_obj     = (const float*)d_in[5];
    const float* b_obj     = (const float*)d_in[6];
    float* out = (float*)d_out;

    (void)in_sizes; (void)n_in; (void)out_size;

    cudaFuncSetAttribute(pool_kernel,
                         cudaFuncAttributeMaxDynamicSharedMemorySize,
                         POOL_SMEM_BYTES);
    pool_kernel<<<dim3(NCHUNK, 4), 512, POOL_SMEM_BYTES>>>(proposals, input_xyz, seg_feats);
    reduce_kernel<<<PPROP, 256>>>(W_cls, b_cls, W_obj, b_obj);
    softmax_kernel<<<1, 256>>>(out);
}